// round 2
// baseline (speedup 1.0000x reference)
#include <cuda_runtime.h>
#include <math.h>

#define Bdim 4
#define Ldim 1024
#define Hdim 16
#define Ddim 64
#define HIDdim 1024
#define BHdim (Bdim*Hdim)

// Scratch intermediates (allocation-free rule: __device__ globals)
__device__ float g_q[BHdim*Ldim*Ddim];
__device__ float g_k[BHdim*Ldim*Ddim];
__device__ float g_v[BHdim*Ldim*Ddim];
__device__ float g_att[BHdim*Ldim*Ddim];

// ---------------------------------------------------------------------------
// Generic GEMM: C[M=4096, N=1024] = A @ W^T + bias
//   A: [4096,1024] row-major (AMODE 0) or gathered from g_att head-split (AMODE 1)
//   W: [N,K] = [1024,1024] row-major (torch Linear weight)
//   C: split-head [BH,L,D] (CMODE 0, DST selects g_q/g_k/g_v) or plain [4096,1024] (CMODE 1)
// Tiling: 128x128x16, 256 threads, 8x8 per-thread microtile.
// ---------------------------------------------------------------------------
template<int AMODE, int CMODE, int DST>
__global__ void __launch_bounds__(256) gemm_kernel(
    const float* __restrict__ A,
    const float* __restrict__ W,
    const float* __restrict__ bias,
    float* __restrict__ Cout)
{
    __shared__ float As[16][128];
    __shared__ float Bs[16][128];
    const int M0 = blockIdx.y * 128;
    const int N0 = blockIdx.x * 128;
    const int tid = threadIdx.x;
    const int ty = tid >> 4;          // 0..15
    const int tx = tid & 15;          // 0..15
    const int lr = tid >> 2;          // 0..63
    const int lc = (tid & 3) << 2;    // 0,4,8,12

    float acc[8][8];
    #pragma unroll
    for (int i = 0; i < 8; i++)
        #pragma unroll
        for (int j = 0; j < 8; j++) acc[i][j] = 0.f;

    for (int k0 = 0; k0 < 1024; k0 += 16) {
        #pragma unroll
        for (int p = 0; p < 2; p++) {
            const int m = M0 + lr + p*64;
            float4 va;
            if (AMODE == 0) {
                va = *(const float4*)(A + (size_t)m*1024 + k0 + lc);
            } else {
                const int bi = m >> 10, l = m & 1023;
                const int kk = k0 + lc;
                const int h = kk >> 6, d = kk & 63;
                va = *(const float4*)(g_att + (((size_t)(bi*Hdim + h))*Ldim + l)*Ddim + d);
            }
            As[lc+0][lr+p*64] = va.x;
            As[lc+1][lr+p*64] = va.y;
            As[lc+2][lr+p*64] = va.z;
            As[lc+3][lr+p*64] = va.w;

            const int n = N0 + lr + p*64;
            const float4 vw = *(const float4*)(W + (size_t)n*1024 + k0 + lc);
            Bs[lc+0][lr+p*64] = vw.x;
            Bs[lc+1][lr+p*64] = vw.y;
            Bs[lc+2][lr+p*64] = vw.z;
            Bs[lc+3][lr+p*64] = vw.w;
        }
        __syncthreads();

        #pragma unroll
        for (int kk = 0; kk < 16; kk++) {
            float a[8], b[8];
            *(float4*)&a[0] = *(const float4*)&As[kk][ty*8];
            *(float4*)&a[4] = *(const float4*)&As[kk][ty*8+4];
            *(float4*)&b[0] = *(const float4*)&Bs[kk][tx*8];
            *(float4*)&b[4] = *(const float4*)&Bs[kk][tx*8+4];
            #pragma unroll
            for (int i = 0; i < 8; i++)
                #pragma unroll
                for (int j = 0; j < 8; j++)
                    acc[i][j] += a[i] * b[j];
        }
        __syncthreads();
    }

    float* dst;
    if (CMODE == 1) dst = Cout;
    else dst = (DST == 0) ? g_q : (DST == 1) ? g_k : g_v;

    #pragma unroll
    for (int i = 0; i < 8; i++) {
        const int m = M0 + ty*8 + i;
        #pragma unroll
        for (int j = 0; j < 8; j++) {
            const int n = N0 + tx*8 + j;
            const float v = acc[i][j] + bias[n];
            if (CMODE == 1) {
                dst[(size_t)m*1024 + n] = v;
            } else {
                const int bi = m >> 10, l = m & 1023;
                const int h = n >> 6, d = n & 63;
                dst[(((size_t)(bi*Hdim + h))*Ldim + l)*Ddim + d] = v;
            }
        }
    }
}

// ---------------------------------------------------------------------------
// scores[bh] = prev[bh]*sigmoid(gat) + (1-sigmoid(gat)) * (q[bh] @ k[bh]^T)
// Tiling: 128x128 output tile, K=64 staged in two 32-wide chunks, 256 threads,
// 8x8 per-thread microtile.
// ---------------------------------------------------------------------------
__global__ void __launch_bounds__(256) scores_kernel(
    const float* __restrict__ prev,
    const float* __restrict__ gat,
    float* __restrict__ scores)
{
    __shared__ float Qs[32][128];
    __shared__ float Ks[32][128];
    const int bh = blockIdx.z;
    const int q0 = blockIdx.y * 128;
    const int k0 = blockIdx.x * 128;
    const int tid = threadIdx.x;
    const int ty = tid >> 4;
    const int tx = tid & 15;
    const int lr = tid >> 3;          // 0..31
    const int lc = (tid & 7) << 2;    // 0..28

    float acc[8][8];
    #pragma unroll
    for (int i = 0; i < 8; i++)
        #pragma unroll
        for (int j = 0; j < 8; j++) acc[i][j] = 0.f;

    const float* qbase = g_q + (size_t)bh * Ldim * Ddim;
    const float* kbase = g_k + (size_t)bh * Ldim * Ddim;

    #pragma unroll
    for (int kt = 0; kt < 64; kt += 32) {
        #pragma unroll
        for (int p = 0; p < 4; p++) {
            const int r = lr + p*32;
            const float4 vq = *(const float4*)(qbase + (size_t)(q0 + r)*Ddim + kt + lc);
            Qs[lc+0][r] = vq.x; Qs[lc+1][r] = vq.y; Qs[lc+2][r] = vq.z; Qs[lc+3][r] = vq.w;
            const float4 vk = *(const float4*)(kbase + (size_t)(k0 + r)*Ddim + kt + lc);
            Ks[lc+0][r] = vk.x; Ks[lc+1][r] = vk.y; Ks[lc+2][r] = vk.z; Ks[lc+3][r] = vk.w;
        }
        __syncthreads();

        #pragma unroll
        for (int kk = 0; kk < 32; kk++) {
            float a[8], b[8];
            *(float4*)&a[0] = *(const float4*)&Qs[kk][ty*8];
            *(float4*)&a[4] = *(const float4*)&Qs[kk][ty*8+4];
            *(float4*)&b[0] = *(const float4*)&Ks[kk][tx*8];
            *(float4*)&b[4] = *(const float4*)&Ks[kk][tx*8+4];
            #pragma unroll
            for (int i = 0; i < 8; i++)
                #pragma unroll
                for (int j = 0; j < 8; j++)
                    acc[i][j] += a[i] * b[j];
        }
        __syncthreads();
    }

    const float g = 1.f / (1.f + expf(-gat[0]));
    const float og = 1.f - g;
    const size_t base = ((size_t)bh << 20);

    #pragma unroll
    for (int i = 0; i < 8; i++) {
        const int m = q0 + ty*8 + i;
        #pragma unroll
        for (int j = 0; j < 8; j++) {
            const int n = k0 + tx*8 + j;
            const size_t idx = base + (size_t)m*Ldim + n;
            scores[idx] = prev[idx] * g + og * acc[i][j];
        }
    }
}

// ---------------------------------------------------------------------------
// Fused masked softmax + P@V (online softmax, flash-style).
// Block: 64 query rows of one head; 256 threads = 64 rows x 4 threads/row,
// each thread owns 16 of the 64 output dims. Key dim chunked by 64.
// Mask semantics (exactly replicating jnp.tile(mask,(H,1))):
//   valid length for (bh, qrow) = mask[bh % 4][qrow]; masked -> exp == 0.
// NOTE: mask is int32 on device (JAX x64 disabled downcasts the requested
// int64 to int32).
// Writes att -> g_att.
// ---------------------------------------------------------------------------
__global__ void __launch_bounds__(256) softmax_av_kernel(
    const float* __restrict__ scores,
    const int* __restrict__ mask)
{
    __shared__ float Ss[64][68];   // padded: rows 16B-aligned, bank-shifted
    __shared__ float Vs[64][64];
    const int bh = blockIdx.y;
    const int q0 = blockIdx.x * 64;
    const int tid = threadIdx.x;
    const int row = tid >> 2;            // 0..63
    const int dbase = (tid & 3) << 4;    // 0,16,32,48
    const int lr = tid >> 4;             // 0..15
    const int lc = (tid & 15) << 2;      // 0..60

    const int* mrow = mask + (size_t)(bh & 3) * Ldim + q0;
    const float* sbase = scores + ((size_t)bh << 20);
    const float* vbase = g_v + (size_t)bh * Ldim * Ddim;

    float mi = -1e30f, li = 0.f;
    float acc[16];
    #pragma unroll
    for (int dd = 0; dd < 16; dd++) acc[dd] = 0.f;

    for (int ck = 0; ck < 16; ck++) {
        const int kk0 = ck * 64;
        #pragma unroll
        for (int p = 0; p < 4; p++) {
            const int r = lr + p*16;
            const int vl = mrow[r];
            const float4 sv = *(const float4*)(sbase + (size_t)(q0 + r)*Ldim + kk0 + lc);
            float4 sm;
            sm.x = (kk0 + lc + 0 < vl) ? sv.x * 0.125f : -1e30f;
            sm.y = (kk0 + lc + 1 < vl) ? sv.y * 0.125f : -1e30f;
            sm.z = (kk0 + lc + 2 < vl) ? sv.z * 0.125f : -1e30f;
            sm.w = (kk0 + lc + 3 < vl) ? sv.w * 0.125f : -1e30f;
            *(float4*)&Ss[r][lc] = sm;
            const float4 vv = *(const float4*)(vbase + (size_t)(kk0 + r)*Ddim + lc);
            *(float4*)&Vs[r][lc] = vv;
        }
        __syncthreads();

        float cmax = -1e30f;
        #pragma unroll
        for (int j = 0; j < 64; j += 4) {
            const float4 s4 = *(const float4*)&Ss[row][j];
            cmax = fmaxf(cmax, fmaxf(fmaxf(s4.x, s4.y), fmaxf(s4.z, s4.w)));
        }
        const float mnew = fmaxf(mi, cmax);
        const float corr = __expf(mi - mnew);
        li *= corr;
        #pragma unroll
        for (int dd = 0; dd < 16; dd++) acc[dd] *= corr;

        #pragma unroll 8
        for (int j = 0; j < 64; j++) {
            const float p = __expf(Ss[row][j] - mnew);
            li += p;
            const float4 v0 = *(const float4*)&Vs[j][dbase];
            const float4 v1 = *(const float4*)&Vs[j][dbase + 4];
            const float4 v2 = *(const float4*)&Vs[j][dbase + 8];
            const float4 v3 = *(const float4*)&Vs[j][dbase + 12];
            acc[0]  += p * v0.x;  acc[1]  += p * v0.y;  acc[2]  += p * v0.z;  acc[3]  += p * v0.w;
            acc[4]  += p * v1.x;  acc[5]  += p * v1.y;  acc[6]  += p * v1.z;  acc[7]  += p * v1.w;
            acc[8]  += p * v2.x;  acc[9]  += p * v2.y;  acc[10] += p * v2.z;  acc[11] += p * v2.w;
            acc[12] += p * v3.x;  acc[13] += p * v3.y;  acc[14] += p * v3.z;  acc[15] += p * v3.w;
        }
        mi = mnew;
        __syncthreads();
    }

    const float inv = 1.f / li;
    float* obase = g_att + (size_t)bh * Ldim * Ddim + (size_t)(q0 + row) * Ddim + dbase;
    #pragma unroll
    for (int dd = 0; dd < 16; dd += 4) {
        float4 o;
        o.x = acc[dd+0] * inv; o.y = acc[dd+1] * inv;
        o.z = acc[dd+2] * inv; o.w = acc[dd+3] * inv;
        *(float4*)(obase + dd) = o;
    }
}

// ---------------------------------------------------------------------------
// Launch
// Inputs (metadata order): queries, keys, values, prev, mask(int32),
//   Wq_w, Wq_b, Wk_w, Wk_b, Wv_w, Wv_b, Wo_w, Wo_b, gat
// Output: [out (4*1024*1024 floats) | scores (64*1024*1024 floats)]
// ---------------------------------------------------------------------------
extern "C" void kernel_launch(void* const* d_in, const int* in_sizes, int n_in,
                              void* d_out, int out_size)
{
    (void)in_sizes; (void)n_in; (void)out_size;
    const float* queries = (const float*)d_in[0];
    const float* keys    = (const float*)d_in[1];
    const float* values  = (const float*)d_in[2];
    const float* prev    = (const float*)d_in[3];
    const int*   mask    = (const int*)d_in[4];
    const float* Wq_w = (const float*)d_in[5];
    const float* Wq_b = (const float*)d_in[6];
    const float* Wk_w = (const float*)d_in[7];
    const float* Wk_b = (const float*)d_in[8];
    const float* Wv_w = (const float*)d_in[9];
    const float* Wv_b = (const float*)d_in[10];
    const float* Wo_w = (const float*)d_in[11];
    const float* Wo_b = (const float*)d_in[12];
    const float* gat  = (const float*)d_in[13];

    float* out    = (float*)d_out;
    float* scores = out + (size_t)Bdim * Ldim * HIDdim;

    dim3 gproj(8, 32);
    gemm_kernel<0, 0, 0><<<gproj, 256>>>(queries, Wq_w, Wq_b, nullptr);
    gemm_kernel<0, 0, 1><<<gproj, 256>>>(keys,    Wk_w, Wk_b, nullptr);
    gemm_kernel<0, 0, 2><<<gproj, 256>>>(values,  Wv_w, Wv_b, nullptr);

    dim3 gsc(8, 8, 64);
    scores_kernel<<<gsc, 256>>>(prev, gat, scores);

    dim3 gsm(16, 64);
    softmax_av_kernel<<<gsm, 256>>>(scores, mask);

    gemm_kernel<1, 1, 3><<<gproj, 256>>>(queries /*unused*/, Wo_w, Wo_b, out);
}

// round 3
// speedup vs baseline: 1.6418x; 1.6418x over previous
#include <cuda_runtime.h>
#include <math.h>

#define Bdim 4
#define Ldim 1024
#define Hdim 16
#define Ddim 64
#define HIDdim 1024
#define BHdim (Bdim*Hdim)

// Scratch intermediates (allocation-free rule: __device__ globals)
__device__ float g_q[BHdim*Ldim*Ddim];
__device__ float g_k[BHdim*Ldim*Ddim];
__device__ float g_v[BHdim*Ldim*Ddim];
__device__ float g_att[BHdim*Ldim*Ddim];

__device__ __forceinline__ unsigned f2tf32(float x) {
    unsigned r;
    asm("cvt.rna.tf32.f32 %0, %1;" : "=r"(r) : "f"(x));
    return r;
}

__device__ __forceinline__ void mma_tf32(
    float& c0, float& c1, float& c2, float& c3,
    unsigned a0, unsigned a1, unsigned a2, unsigned a3,
    unsigned b0, unsigned b1)
{
    asm volatile(
        "mma.sync.aligned.m16n8k8.row.col.f32.tf32.tf32.f32 "
        "{%0,%1,%2,%3}, {%4,%5,%6,%7}, {%8,%9}, {%0,%1,%2,%3};"
        : "+f"(c0), "+f"(c1), "+f"(c2), "+f"(c3)
        : "r"(a0), "r"(a1), "r"(a2), "r"(a3), "r"(b0), "r"(b1));
}

// ---------------------------------------------------------------------------
// Tensor-core GEMM: C[M=4096, N=1024] = A @ W^T + bias  (tf32 mma.sync)
//   A: [4096,1024] row-major (AMODE 0) or gathered from g_att head-split (AMODE 1)
//   W: [N,K] row-major (torch Linear weight) == B col-major for mma
//   C: split-head [BH,L,D] (CMODE 0, DST 0/1/2 -> g_q/g_k/g_v) or [4096,1024] (CMODE 1)
// Block tile 128x128x32, 256 threads (8 warps: 2m x 4n), warp tile 64x32,
// fragment grid per warp: 4 x (m16) x 4 x (n8), k-steps of 8.
// ---------------------------------------------------------------------------
template<int AMODE, int CMODE, int DST>
__global__ void __launch_bounds__(256) gemm_tc(
    const float* __restrict__ A,
    const float* __restrict__ W,
    const float* __restrict__ bias,
    float* __restrict__ Cout)
{
    __shared__ unsigned As[128][36];   // [m][k] padded: bank = (4g+t) conflict-free
    __shared__ unsigned Ws[128][36];   // [n][k] padded

    const int M0 = blockIdx.y * 128;
    const int N0 = blockIdx.x * 128;
    const int tid = threadIdx.x;
    const int wid = tid >> 5;
    const int lane = tid & 31;
    const int grp = lane >> 2;        // 0..7
    const int tig = lane & 3;         // 0..3
    const int wm = wid >> 2;          // 0..1 -> 64 rows
    const int wn = wid & 3;           // 0..3 -> 32 cols

    float c[4][4][4];
    #pragma unroll
    for (int mi = 0; mi < 4; mi++)
        #pragma unroll
        for (int ni = 0; ni < 4; ni++)
            #pragma unroll
            for (int r = 0; r < 4; r++) c[mi][ni][r] = 0.f;

    for (int k0 = 0; k0 < 1024; k0 += 32) {
        // Fill As / Ws: 128 rows x 32 cols each; 4 float4 per thread per matrix.
        #pragma unroll
        for (int p = 0; p < 4; p++) {
            const int idx = tid + p * 256;
            const int m = idx >> 3;
            const int cc = (idx & 7) << 2;
            float4 va;
            if (AMODE == 0) {
                va = *(const float4*)(A + (size_t)(M0 + m) * 1024 + k0 + cc);
            } else {
                const int gm = M0 + m;
                const int bi = gm >> 10, l = gm & 1023;
                const int kk = k0 + cc;
                const int h = kk >> 6, d = kk & 63;
                va = *(const float4*)(g_att + (((size_t)(bi * Hdim + h)) * Ldim + l) * Ddim + d);
            }
            unsigned ua[4] = { f2tf32(va.x), f2tf32(va.y), f2tf32(va.z), f2tf32(va.w) };
            *(uint4*)&As[m][cc] = *(uint4*)ua;

            const float4 vw = *(const float4*)(W + (size_t)(N0 + m) * 1024 + k0 + cc);
            unsigned uw[4] = { f2tf32(vw.x), f2tf32(vw.y), f2tf32(vw.z), f2tf32(vw.w) };
            *(uint4*)&Ws[m][cc] = *(uint4*)uw;
        }
        __syncthreads();

        #pragma unroll
        for (int ks = 0; ks < 4; ks++) {
            const int kk = ks * 8;
            unsigned af[4][4], bf[4][2];
            #pragma unroll
            for (int mi = 0; mi < 4; mi++) {
                const int r = wm * 64 + mi * 16 + grp;
                af[mi][0] = As[r][kk + tig];
                af[mi][1] = As[r + 8][kk + tig];
                af[mi][2] = As[r][kk + tig + 4];
                af[mi][3] = As[r + 8][kk + tig + 4];
            }
            #pragma unroll
            for (int ni = 0; ni < 4; ni++) {
                const int n = wn * 32 + ni * 8 + grp;
                bf[ni][0] = Ws[n][kk + tig];
                bf[ni][1] = Ws[n][kk + tig + 4];
            }
            #pragma unroll
            for (int mi = 0; mi < 4; mi++)
                #pragma unroll
                for (int ni = 0; ni < 4; ni++)
                    mma_tf32(c[mi][ni][0], c[mi][ni][1], c[mi][ni][2], c[mi][ni][3],
                             af[mi][0], af[mi][1], af[mi][2], af[mi][3],
                             bf[ni][0], bf[ni][1]);
        }
        __syncthreads();
    }

    float* dst;
    if (CMODE == 1) dst = Cout;
    else dst = (DST == 0) ? g_q : (DST == 1) ? g_k : g_v;

    #pragma unroll
    for (int mi = 0; mi < 4; mi++) {
        #pragma unroll
        for (int ni = 0; ni < 4; ni++) {
            const int r0 = M0 + wm * 64 + mi * 16 + grp;
            const int r1 = r0 + 8;
            const int cn = N0 + wn * 32 + ni * 8 + tig * 2;
            const float bv0 = bias[cn], bv1 = bias[cn + 1];
            float2 v0 = make_float2(c[mi][ni][0] + bv0, c[mi][ni][1] + bv1);
            float2 v1 = make_float2(c[mi][ni][2] + bv0, c[mi][ni][3] + bv1);
            if (CMODE == 1) {
                *(float2*)(dst + (size_t)r0 * 1024 + cn) = v0;
                *(float2*)(dst + (size_t)r1 * 1024 + cn) = v1;
            } else {
                const int h = cn >> 6, d = cn & 63;
                const int bi0 = r0 >> 10, l0 = r0 & 1023;
                const int bi1 = r1 >> 10, l1 = r1 & 1023;
                *(float2*)(dst + (((size_t)(bi0 * Hdim + h)) * Ldim + l0) * Ddim + d) = v0;
                *(float2*)(dst + (((size_t)(bi1 * Hdim + h)) * Ldim + l1) * Ddim + d) = v1;
            }
        }
    }
}

// ---------------------------------------------------------------------------
// Tensor-core scores: scores[bh] = prev*sig(gat) + (1-sig(gat)) * q[bh] @ k[bh]^T
// Same tiling as gemm_tc but K=64 (two 32-wide k-tiles), A/B row stride 64.
// ---------------------------------------------------------------------------
__global__ void __launch_bounds__(256) scores_tc(
    const float* __restrict__ prev,
    const float* __restrict__ gat,
    float* __restrict__ scores)
{
    __shared__ unsigned As[128][36];
    __shared__ unsigned Ws[128][36];

    const int bh = blockIdx.z;
    const int M0 = blockIdx.y * 128;   // q rows
    const int N0 = blockIdx.x * 128;   // k rows
    const int tid = threadIdx.x;
    const int wid = tid >> 5;
    const int lane = tid & 31;
    const int grp = lane >> 2;
    const int tig = lane & 3;
    const int wm = wid >> 2;
    const int wn = wid & 3;

    const float* qbase = g_q + (size_t)bh * Ldim * Ddim;
    const float* kbase = g_k + (size_t)bh * Ldim * Ddim;

    float c[4][4][4];
    #pragma unroll
    for (int mi = 0; mi < 4; mi++)
        #pragma unroll
        for (int ni = 0; ni < 4; ni++)
            #pragma unroll
            for (int r = 0; r < 4; r++) c[mi][ni][r] = 0.f;

    #pragma unroll
    for (int k0 = 0; k0 < 64; k0 += 32) {
        #pragma unroll
        for (int p = 0; p < 4; p++) {
            const int idx = tid + p * 256;
            const int m = idx >> 3;
            const int cc = (idx & 7) << 2;
            const float4 va = *(const float4*)(qbase + (size_t)(M0 + m) * Ddim + k0 + cc);
            unsigned ua[4] = { f2tf32(va.x), f2tf32(va.y), f2tf32(va.z), f2tf32(va.w) };
            *(uint4*)&As[m][cc] = *(uint4*)ua;
            const float4 vk = *(const float4*)(kbase + (size_t)(N0 + m) * Ddim + k0 + cc);
            unsigned uk[4] = { f2tf32(vk.x), f2tf32(vk.y), f2tf32(vk.z), f2tf32(vk.w) };
            *(uint4*)&Ws[m][cc] = *(uint4*)uk;
        }
        __syncthreads();

        #pragma unroll
        for (int ks = 0; ks < 4; ks++) {
            const int kk = ks * 8;
            unsigned af[4][4], bf[4][2];
            #pragma unroll
            for (int mi = 0; mi < 4; mi++) {
                const int r = wm * 64 + mi * 16 + grp;
                af[mi][0] = As[r][kk + tig];
                af[mi][1] = As[r + 8][kk + tig];
                af[mi][2] = As[r][kk + tig + 4];
                af[mi][3] = As[r + 8][kk + tig + 4];
            }
            #pragma unroll
            for (int ni = 0; ni < 4; ni++) {
                const int n = wn * 32 + ni * 8 + grp;
                bf[ni][0] = Ws[n][kk + tig];
                bf[ni][1] = Ws[n][kk + tig + 4];
            }
            #pragma unroll
            for (int mi = 0; mi < 4; mi++)
                #pragma unroll
                for (int ni = 0; ni < 4; ni++)
                    mma_tf32(c[mi][ni][0], c[mi][ni][1], c[mi][ni][2], c[mi][ni][3],
                             af[mi][0], af[mi][1], af[mi][2], af[mi][3],
                             bf[ni][0], bf[ni][1]);
        }
        __syncthreads();
    }

    const float g = 1.f / (1.f + __expf(-gat[0]));
    const float og = 1.f - g;
    const size_t base = ((size_t)bh << 20);

    #pragma unroll
    for (int mi = 0; mi < 4; mi++) {
        #pragma unroll
        for (int ni = 0; ni < 4; ni++) {
            const int r0 = M0 + wm * 64 + mi * 16 + grp;
            const int r1 = r0 + 8;
            const int cn = N0 + wn * 32 + ni * 8 + tig * 2;
            const size_t i0 = base + (size_t)r0 * Ldim + cn;
            const size_t i1 = base + (size_t)r1 * Ldim + cn;
            const float2 p0 = *(const float2*)(prev + i0);
            const float2 p1 = *(const float2*)(prev + i1);
            float2 s0 = make_float2(p0.x * g + og * c[mi][ni][0],
                                    p0.y * g + og * c[mi][ni][1]);
            float2 s1 = make_float2(p1.x * g + og * c[mi][ni][2],
                                    p1.y * g + og * c[mi][ni][3]);
            *(float2*)(scores + i0) = s0;
            *(float2*)(scores + i1) = s1;
        }
    }
}

// ---------------------------------------------------------------------------
// Fused masked softmax + P@V (online softmax). Unchanged from passing R2.
// mask is int32 on device. valid length for (bh,qrow) = mask[bh % 4][qrow].
// ---------------------------------------------------------------------------
__global__ void __launch_bounds__(256) softmax_av_kernel(
    const float* __restrict__ scores,
    const int* __restrict__ mask)
{
    __shared__ float Ss[64][68];
    __shared__ float Vs[64][64];
    const int bh = blockIdx.y;
    const int q0 = blockIdx.x * 64;
    const int tid = threadIdx.x;
    const int row = tid >> 2;
    const int dbase = (tid & 3) << 4;
    const int lr = tid >> 4;
    const int lc = (tid & 15) << 2;

    const int* mrow = mask + (size_t)(bh & 3) * Ldim + q0;
    const float* sbase = scores + ((size_t)bh << 20);
    const float* vbase = g_v + (size_t)bh * Ldim * Ddim;

    float mi = -1e30f, li = 0.f;
    float acc[16];
    #pragma unroll
    for (int dd = 0; dd < 16; dd++) acc[dd] = 0.f;

    for (int ck = 0; ck < 16; ck++) {
        const int kk0 = ck * 64;
        #pragma unroll
        for (int p = 0; p < 4; p++) {
            const int r = lr + p*16;
            const int vl = mrow[r];
            const float4 sv = *(const float4*)(sbase + (size_t)(q0 + r)*Ldim + kk0 + lc);
            float4 sm;
            sm.x = (kk0 + lc + 0 < vl) ? sv.x * 0.125f : -1e30f;
            sm.y = (kk0 + lc + 1 < vl) ? sv.y * 0.125f : -1e30f;
            sm.z = (kk0 + lc + 2 < vl) ? sv.z * 0.125f : -1e30f;
            sm.w = (kk0 + lc + 3 < vl) ? sv.w * 0.125f : -1e30f;
            *(float4*)&Ss[r][lc] = sm;
            const float4 vv = *(const float4*)(vbase + (size_t)(kk0 + r)*Ddim + lc);
            *(float4*)&Vs[r][lc] = vv;
        }
        __syncthreads();

        float cmax = -1e30f;
        #pragma unroll
        for (int j = 0; j < 64; j += 4) {
            const float4 s4 = *(const float4*)&Ss[row][j];
            cmax = fmaxf(cmax, fmaxf(fmaxf(s4.x, s4.y), fmaxf(s4.z, s4.w)));
        }
        const float mnew = fmaxf(mi, cmax);
        const float corr = __expf(mi - mnew);
        li *= corr;
        #pragma unroll
        for (int dd = 0; dd < 16; dd++) acc[dd] *= corr;

        #pragma unroll 8
        for (int j = 0; j < 64; j++) {
            const float p = __expf(Ss[row][j] - mnew);
            li += p;
            const float4 v0 = *(const float4*)&Vs[j][dbase];
            const float4 v1 = *(const float4*)&Vs[j][dbase + 4];
            const float4 v2 = *(const float4*)&Vs[j][dbase + 8];
            const float4 v3 = *(const float4*)&Vs[j][dbase + 12];
            acc[0]  += p * v0.x;  acc[1]  += p * v0.y;  acc[2]  += p * v0.z;  acc[3]  += p * v0.w;
            acc[4]  += p * v1.x;  acc[5]  += p * v1.y;  acc[6]  += p * v1.z;  acc[7]  += p * v1.w;
            acc[8]  += p * v2.x;  acc[9]  += p * v2.y;  acc[10] += p * v2.z;  acc[11] += p * v2.w;
            acc[12] += p * v3.x;  acc[13] += p * v3.y;  acc[14] += p * v3.z;  acc[15] += p * v3.w;
        }
        mi = mnew;
        __syncthreads();
    }

    const float inv = 1.f / li;
    float* obase = g_att + (size_t)bh * Ldim * Ddim + (size_t)(q0 + row) * Ddim + dbase;
    #pragma unroll
    for (int dd = 0; dd < 16; dd += 4) {
        float4 o;
        o.x = acc[dd+0] * inv; o.y = acc[dd+1] * inv;
        o.z = acc[dd+2] * inv; o.w = acc[dd+3] * inv;
        *(float4*)(obase + dd) = o;
    }
}

// ---------------------------------------------------------------------------
// Launch.  Inputs: queries, keys, values, prev, mask(int32),
//   Wq_w, Wq_b, Wk_w, Wk_b, Wv_w, Wv_b, Wo_w, Wo_b, gat
// Output: [out (4M floats) | scores (64M floats)]
// ---------------------------------------------------------------------------
extern "C" void kernel_launch(void* const* d_in, const int* in_sizes, int n_in,
                              void* d_out, int out_size)
{
    (void)in_sizes; (void)n_in; (void)out_size;
    const float* queries = (const float*)d_in[0];
    const float* keys    = (const float*)d_in[1];
    const float* values  = (const float*)d_in[2];
    const float* prev    = (const float*)d_in[3];
    const int*   mask    = (const int*)d_in[4];
    const float* Wq_w = (const float*)d_in[5];
    const float* Wq_b = (const float*)d_in[6];
    const float* Wk_w = (const float*)d_in[7];
    const float* Wk_b = (const float*)d_in[8];
    const float* Wv_w = (const float*)d_in[9];
    const float* Wv_b = (const float*)d_in[10];
    const float* Wo_w = (const float*)d_in[11];
    const float* Wo_b = (const float*)d_in[12];
    const float* gat  = (const float*)d_in[13];

    float* out    = (float*)d_out;
    float* scores = out + (size_t)Bdim * Ldim * HIDdim;

    dim3 gproj(8, 32);
    gemm_tc<0, 0, 0><<<gproj, 256>>>(queries, Wq_w, Wq_b, nullptr);
    gemm_tc<0, 0, 1><<<gproj, 256>>>(keys,    Wk_w, Wk_b, nullptr);
    gemm_tc<0, 0, 2><<<gproj, 256>>>(values,  Wv_w, Wv_b, nullptr);

    dim3 gsc(8, 8, 64);
    scores_tc<<<gsc, 256>>>(prev, gat, scores);

    dim3 gsm(16, 64);
    softmax_av_kernel<<<gsm, 256>>>(scores, mask);

    gemm_tc<1, 1, 3><<<gproj, 256>>>(queries /*unused*/, Wo_w, Wo_b, out);
}

// round 4
// speedup vs baseline: 4.3343x; 2.6399x over previous
#include <cuda_runtime.h>
#include <math.h>

#define Bdim 4
#define Ldim 1024
#define Hdim 16
#define Ddim 64
#define HIDdim 1024
#define BHdim (Bdim*Hdim)

// Scratch intermediates (allocation-free rule: __device__ globals)
__device__ float g_q[BHdim*Ldim*Ddim];
__device__ float g_k[BHdim*Ldim*Ddim];
__device__ float g_v[BHdim*Ldim*Ddim];   // stored TRANSPOSED: [BH][D][L]
__device__ float g_att[BHdim*Ldim*Ddim]; // [BH][L][D]

__device__ __forceinline__ unsigned f2tf32(float x) {
    unsigned r;
    asm("cvt.rna.tf32.f32 %0, %1;" : "=r"(r) : "f"(x));
    return r;
}

__device__ __forceinline__ void mma_tf32(
    float& c0, float& c1, float& c2, float& c3,
    unsigned a0, unsigned a1, unsigned a2, unsigned a3,
    unsigned b0, unsigned b1)
{
    asm volatile(
        "mma.sync.aligned.m16n8k8.row.col.f32.tf32.tf32.f32 "
        "{%0,%1,%2,%3}, {%4,%5,%6,%7}, {%8,%9}, {%0,%1,%2,%3};"
        : "+f"(c0), "+f"(c1), "+f"(c2), "+f"(c3)
        : "r"(a0), "r"(a1), "r"(a2), "r"(a3), "r"(b0), "r"(b1));
}

// ---------------------------------------------------------------------------
// Tensor-core GEMM: C[M, N] = A @ W^T + bias  (tf32 mma.sync), K = 1024
//   AMODE 0: A row-major [M,1024]; AMODE 1: A gathered from g_att head-split
//   CMODE 0: split-head store to g_q/g_k (DST 0/1), bias indexed by col
//   CMODE 1: plain [M,1024] store to Cout, bias indexed by col
//   CMODE 2: transposed-V store: here M=1024 (hid dims), N=4096 (tokens);
//            bias indexed by ROW; store to g_v[(col>>10)*1M + row*1024 + (col&1023)]
// Block tile 128x128x32, 256 threads (8 warps 2m x 4n), warp tile 64x32.
// ---------------------------------------------------------------------------
template<int AMODE, int CMODE, int DST>
__global__ void __launch_bounds__(256) gemm_tc(
    const float* __restrict__ A,
    const float* __restrict__ W,
    const float* __restrict__ bias,
    float* __restrict__ Cout)
{
    __shared__ unsigned As[128][36];
    __shared__ unsigned Ws[128][36];

    const int M0 = blockIdx.y * 128;
    const int N0 = blockIdx.x * 128;
    const int tid = threadIdx.x;
    const int wid = tid >> 5;
    const int lane = tid & 31;
    const int grp = lane >> 2;
    const int tig = lane & 3;
    const int wm = wid >> 2;
    const int wn = wid & 3;

    float c[4][4][4];
    #pragma unroll
    for (int mi = 0; mi < 4; mi++)
        #pragma unroll
        for (int ni = 0; ni < 4; ni++)
            #pragma unroll
            for (int r = 0; r < 4; r++) c[mi][ni][r] = 0.f;

    for (int k0 = 0; k0 < 1024; k0 += 32) {
        #pragma unroll
        for (int p = 0; p < 4; p++) {
            const int idx = tid + p * 256;
            const int m = idx >> 3;
            const int cc = (idx & 7) << 2;
            float4 va;
            if (AMODE == 0) {
                va = *(const float4*)(A + (size_t)(M0 + m) * 1024 + k0 + cc);
            } else {
                const int gm = M0 + m;
                const int bi = gm >> 10, l = gm & 1023;
                const int kk = k0 + cc;
                const int h = kk >> 6, d = kk & 63;
                va = *(const float4*)(g_att + (((size_t)(bi * Hdim + h)) * Ldim + l) * Ddim + d);
            }
            unsigned ua[4] = { f2tf32(va.x), f2tf32(va.y), f2tf32(va.z), f2tf32(va.w) };
            *(uint4*)&As[m][cc] = *(uint4*)ua;

            const float4 vw = *(const float4*)(W + (size_t)(N0 + m) * 1024 + k0 + cc);
            unsigned uw[4] = { f2tf32(vw.x), f2tf32(vw.y), f2tf32(vw.z), f2tf32(vw.w) };
            *(uint4*)&Ws[m][cc] = *(uint4*)uw;
        }
        __syncthreads();

        #pragma unroll
        for (int ks = 0; ks < 4; ks++) {
            const int kk = ks * 8;
            unsigned af[4][4], bf[4][2];
            #pragma unroll
            for (int mi = 0; mi < 4; mi++) {
                const int r = wm * 64 + mi * 16 + grp;
                af[mi][0] = As[r][kk + tig];
                af[mi][1] = As[r + 8][kk + tig];
                af[mi][2] = As[r][kk + tig + 4];
                af[mi][3] = As[r + 8][kk + tig + 4];
            }
            #pragma unroll
            for (int ni = 0; ni < 4; ni++) {
                const int n = wn * 32 + ni * 8 + grp;
                bf[ni][0] = Ws[n][kk + tig];
                bf[ni][1] = Ws[n][kk + tig + 4];
            }
            #pragma unroll
            for (int mi = 0; mi < 4; mi++)
                #pragma unroll
                for (int ni = 0; ni < 4; ni++)
                    mma_tf32(c[mi][ni][0], c[mi][ni][1], c[mi][ni][2], c[mi][ni][3],
                             af[mi][0], af[mi][1], af[mi][2], af[mi][3],
                             bf[ni][0], bf[ni][1]);
        }
        __syncthreads();
    }

    #pragma unroll
    for (int mi = 0; mi < 4; mi++) {
        #pragma unroll
        for (int ni = 0; ni < 4; ni++) {
            const int r0 = M0 + wm * 64 + mi * 16 + grp;
            const int r1 = r0 + 8;
            const int cn = N0 + wn * 32 + ni * 8 + tig * 2;
            if (CMODE == 2) {
                // transposed V: row r = hid dim, col cn = token index
                const float bv0 = bias[r0], bv1 = bias[r1];
                float2 v0 = make_float2(c[mi][ni][0] + bv0, c[mi][ni][1] + bv0);
                float2 v1 = make_float2(c[mi][ni][2] + bv1, c[mi][ni][3] + bv1);
                const size_t base = (size_t)(cn >> 10) * 1048576 + (cn & 1023);
                *(float2*)(g_v + base + (size_t)r0 * 1024) = v0;
                *(float2*)(g_v + base + (size_t)r1 * 1024) = v1;
            } else {
                const float bv0 = bias[cn], bv1 = bias[cn + 1];
                float2 v0 = make_float2(c[mi][ni][0] + bv0, c[mi][ni][1] + bv1);
                float2 v1 = make_float2(c[mi][ni][2] + bv0, c[mi][ni][3] + bv1);
                if (CMODE == 1) {
                    *(float2*)(Cout + (size_t)r0 * 1024 + cn) = v0;
                    *(float2*)(Cout + (size_t)r1 * 1024 + cn) = v1;
                } else {
                    float* dst = (DST == 0) ? g_q : g_k;
                    const int h = cn >> 6, d = cn & 63;
                    const int bi0 = r0 >> 10, l0 = r0 & 1023;
                    const int bi1 = r1 >> 10, l1 = r1 & 1023;
                    *(float2*)(dst + (((size_t)(bi0 * Hdim + h)) * Ldim + l0) * Ddim + d) = v0;
                    *(float2*)(dst + (((size_t)(bi1 * Hdim + h)) * Ldim + l1) * Ddim + d) = v1;
                }
            }
        }
    }
}

// ---------------------------------------------------------------------------
// Fused flash attention: per block = 128 query rows of one head.
// Loop over 64-key tiles: S = Q@K^T (mma) -> blend with prev (write scores)
// -> mask+scale -> online softmax -> P (tf32, smem) -> O += P@V (mma).
// Warp w owns rows [w*16, w*16+16). All row reductions are quad-shuffles.
// smem: uQ[128][68], uK[64][68], uV[64][68] (=V^T tile [d][j]), uP[128][68].
// ---------------------------------------------------------------------------
#define SMEM_FUSED ((128*68 + 64*68 + 64*68 + 128*68) * 4)

__global__ void __launch_bounds__(256, 2) fused_attn(
    const float* __restrict__ prev,
    const int* __restrict__ mask,
    const float* __restrict__ gat,
    float* __restrict__ scores)
{
    extern __shared__ unsigned sm[];
    unsigned* uQ = sm;                   // [128][68]
    unsigned* uK = uQ + 128 * 68;        // [64][68]   K tile [j][d]
    unsigned* uV = uK + 64 * 68;         // [64][68]   V^T tile [d][j]
    unsigned* uP = uV + 64 * 68;         // [128][68]  P tile [row][j]

    const int bh = blockIdx.y;
    const int q0 = blockIdx.x * 128;
    const int tid = threadIdx.x;
    const int w = tid >> 5;
    const int lane = tid & 31;
    const int grp = lane >> 2;
    const int tig = lane & 3;
    const int rw0 = w * 16 + grp;
    const int rw1 = rw0 + 8;
    const int gq0 = q0 + rw0;
    const int gq1 = q0 + rw1;

    const float* qg = g_q + (size_t)bh * Ldim * Ddim;
    const float* kg = g_k + (size_t)bh * Ldim * Ddim;
    const float* vg = g_v + (size_t)bh * Ddim * Ldim;   // transposed [d][l]

    // Load Q tile once (128 x 64)
    #pragma unroll
    for (int p = 0; p < 8; p++) {
        const int idx = tid + p * 256;
        const int m = idx >> 4;
        const int cc = (idx & 15) << 2;
        const float4 va = *(const float4*)(qg + (size_t)(q0 + m) * Ddim + cc);
        unsigned ua[4] = { f2tf32(va.x), f2tf32(va.y), f2tf32(va.z), f2tf32(va.w) };
        *(uint4*)&uQ[m * 68 + cc] = *(uint4*)ua;
    }

    const int vl0 = mask[(bh & 3) * Ldim + gq0];
    const int vl1 = mask[(bh & 3) * Ldim + gq1];
    const float gv = 1.f / (1.f + __expf(-gat[0]));
    const float og = 1.f - gv;
    const size_t sb = ((size_t)bh << 20);

    float o[8][4];
    #pragma unroll
    for (int ni = 0; ni < 8; ni++)
        #pragma unroll
        for (int r = 0; r < 4; r++) o[ni][r] = 0.f;
    float mi0 = -1e30f, mi1 = -1e30f, li0 = 0.f, li1 = 0.f;

    for (int kt = 0; kt < Ldim; kt += 64) {
        // Load K tile [j][d] and V^T tile [d][j] (both 64x64, coalesced)
        #pragma unroll
        for (int p = 0; p < 4; p++) {
            const int idx = tid + p * 256;
            const int r = idx >> 4;
            const int cc = (idx & 15) << 2;
            const float4 vk = *(const float4*)(kg + (size_t)(kt + r) * Ddim + cc);
            unsigned uk[4] = { f2tf32(vk.x), f2tf32(vk.y), f2tf32(vk.z), f2tf32(vk.w) };
            *(uint4*)&uK[r * 68 + cc] = *(uint4*)uk;
            const float4 vv = *(const float4*)(vg + (size_t)r * Ldim + kt + cc);
            unsigned uv[4] = { f2tf32(vv.x), f2tf32(vv.y), f2tf32(vv.z), f2tf32(vv.w) };
            *(uint4*)&uV[r * 68 + cc] = *(uint4*)uv;
        }
        __syncthreads();

        // S = Q @ K^T : warp computes 16 rows x 64 cols
        float cs[8][4];
        #pragma unroll
        for (int ni = 0; ni < 8; ni++)
            #pragma unroll
            for (int r = 0; r < 4; r++) cs[ni][r] = 0.f;

        #pragma unroll
        for (int ks = 0; ks < 8; ks++) {
            const int kk = ks * 8;
            const unsigned a0 = uQ[rw0 * 68 + kk + tig];
            const unsigned a1 = uQ[rw1 * 68 + kk + tig];
            const unsigned a2 = uQ[rw0 * 68 + kk + tig + 4];
            const unsigned a3 = uQ[rw1 * 68 + kk + tig + 4];
            #pragma unroll
            for (int ni = 0; ni < 8; ni++) {
                const unsigned b0 = uK[(ni * 8 + grp) * 68 + kk + tig];
                const unsigned b1 = uK[(ni * 8 + grp) * 68 + kk + tig + 4];
                mma_tf32(cs[ni][0], cs[ni][1], cs[ni][2], cs[ni][3],
                         a0, a1, a2, a3, b0, b1);
            }
        }

        // Epilogue: blend with prev, write scores, mask+scale (in place)
        float m0 = -1e30f, m1 = -1e30f;
        #pragma unroll
        for (int ni = 0; ni < 8; ni++) {
            const int col = kt + ni * 8 + tig * 2;
            const size_t i0 = sb + (size_t)gq0 * Ldim + col;
            const size_t i1 = sb + (size_t)gq1 * Ldim + col;
            const float2 p0 = *(const float2*)(prev + i0);
            const float2 p1 = *(const float2*)(prev + i1);
            const float b00 = p0.x * gv + og * cs[ni][0];
            const float b01 = p0.y * gv + og * cs[ni][1];
            const float b10 = p1.x * gv + og * cs[ni][2];
            const float b11 = p1.y * gv + og * cs[ni][3];
            *(float2*)(scores + i0) = make_float2(b00, b01);
            *(float2*)(scores + i1) = make_float2(b10, b11);
            cs[ni][0] = (col     < vl0) ? b00 * 0.125f : -1e30f;
            cs[ni][1] = (col + 1 < vl0) ? b01 * 0.125f : -1e30f;
            cs[ni][2] = (col     < vl1) ? b10 * 0.125f : -1e30f;
            cs[ni][3] = (col + 1 < vl1) ? b11 * 0.125f : -1e30f;
            m0 = fmaxf(m0, fmaxf(cs[ni][0], cs[ni][1]));
            m1 = fmaxf(m1, fmaxf(cs[ni][2], cs[ni][3]));
        }
        m0 = fmaxf(m0, __shfl_xor_sync(0xffffffffu, m0, 1));
        m0 = fmaxf(m0, __shfl_xor_sync(0xffffffffu, m0, 2));
        m1 = fmaxf(m1, __shfl_xor_sync(0xffffffffu, m1, 1));
        m1 = fmaxf(m1, __shfl_xor_sync(0xffffffffu, m1, 2));

        const float mn0 = fmaxf(mi0, m0);
        const float mn1 = fmaxf(mi1, m1);
        const float cr0 = __expf(mi0 - mn0);
        const float cr1 = __expf(mi1 - mn1);
        li0 *= cr0; li1 *= cr1;
        #pragma unroll
        for (int ni = 0; ni < 8; ni++) {
            o[ni][0] *= cr0; o[ni][1] *= cr0;
            o[ni][2] *= cr1; o[ni][3] *= cr1;
        }
        mi0 = mn0; mi1 = mn1;

        // P = exp(s - m), accumulate partial row sums, store tf32 to uP
        #pragma unroll
        for (int ni = 0; ni < 8; ni++) {
            const float p00 = __expf(cs[ni][0] - mn0);
            const float p01 = __expf(cs[ni][1] - mn0);
            const float p10 = __expf(cs[ni][2] - mn1);
            const float p11 = __expf(cs[ni][3] - mn1);
            li0 += p00 + p01;
            li1 += p10 + p11;
            const int pc = ni * 8 + tig * 2;
            uP[rw0 * 68 + pc]     = f2tf32(p00);
            uP[rw0 * 68 + pc + 1] = f2tf32(p01);
            uP[rw1 * 68 + pc]     = f2tf32(p10);
            uP[rw1 * 68 + pc + 1] = f2tf32(p11);
        }
        __syncwarp();

        // O += P @ V  (P rows owned by this warp; V^T in uV)
        #pragma unroll
        for (int ks = 0; ks < 8; ks++) {
            const int kk = ks * 8;
            const unsigned a0 = uP[rw0 * 68 + kk + tig];
            const unsigned a1 = uP[rw1 * 68 + kk + tig];
            const unsigned a2 = uP[rw0 * 68 + kk + tig + 4];
            const unsigned a3 = uP[rw1 * 68 + kk + tig + 4];
            #pragma unroll
            for (int ni = 0; ni < 8; ni++) {
                const unsigned b0 = uV[(ni * 8 + grp) * 68 + kk + tig];
                const unsigned b1 = uV[(ni * 8 + grp) * 68 + kk + tig + 4];
                mma_tf32(o[ni][0], o[ni][1], o[ni][2], o[ni][3],
                         a0, a1, a2, a3, b0, b1);
            }
        }
        __syncthreads();
    }

    // Final: normalize by row sums and write att
    li0 += __shfl_xor_sync(0xffffffffu, li0, 1);
    li0 += __shfl_xor_sync(0xffffffffu, li0, 2);
    li1 += __shfl_xor_sync(0xffffffffu, li1, 1);
    li1 += __shfl_xor_sync(0xffffffffu, li1, 2);
    const float inv0 = 1.f / li0;
    const float inv1 = 1.f / li1;

    float* ab = g_att + (size_t)bh * Ldim * Ddim;
    #pragma unroll
    for (int ni = 0; ni < 8; ni++) {
        const int d = ni * 8 + tig * 2;
        *(float2*)(ab + (size_t)gq0 * Ddim + d) =
            make_float2(o[ni][0] * inv0, o[ni][1] * inv0);
        *(float2*)(ab + (size_t)gq1 * Ddim + d) =
            make_float2(o[ni][2] * inv1, o[ni][3] * inv1);
    }
}

// ---------------------------------------------------------------------------
// Launch.  Inputs: queries, keys, values, prev, mask(int32),
//   Wq_w, Wq_b, Wk_w, Wk_b, Wv_w, Wv_b, Wo_w, Wo_b, gat
// Output: [out (4M floats) | scores (64M floats)]
// ---------------------------------------------------------------------------
extern "C" void kernel_launch(void* const* d_in, const int* in_sizes, int n_in,
                              void* d_out, int out_size)
{
    (void)in_sizes; (void)n_in; (void)out_size;
    const float* queries = (const float*)d_in[0];
    const float* keys    = (const float*)d_in[1];
    const float* values  = (const float*)d_in[2];
    const float* prev    = (const float*)d_in[3];
    const int*   mask    = (const int*)d_in[4];
    const float* Wq_w = (const float*)d_in[5];
    const float* Wq_b = (const float*)d_in[6];
    const float* Wk_w = (const float*)d_in[7];
    const float* Wk_b = (const float*)d_in[8];
    const float* Wv_w = (const float*)d_in[9];
    const float* Wv_b = (const float*)d_in[10];
    const float* Wo_w = (const float*)d_in[11];
    const float* Wo_b = (const float*)d_in[12];
    const float* gat  = (const float*)d_in[13];

    float* out    = (float*)d_out;
    float* scores = out + (size_t)Bdim * Ldim * HIDdim;

    cudaFuncSetAttribute(fused_attn,
                         cudaFuncAttributeMaxDynamicSharedMemorySize, SMEM_FUSED);

    dim3 gproj(8, 32);
    gemm_tc<0, 0, 0><<<gproj, 256>>>(queries, Wq_w, Wq_b, nullptr);
    gemm_tc<0, 0, 1><<<gproj, 256>>>(keys,    Wk_w, Wk_b, nullptr);
    // V projection computed transposed: C^T = Wv @ values^T
    dim3 gvt(32, 8);
    gemm_tc<0, 2, 2><<<gvt, 256>>>(Wv_w, values, Wv_b, nullptr);

    dim3 gf(8, 64);
    fused_attn<<<gf, 256, SMEM_FUSED>>>(prev, mask, gat, scores);

    gemm_tc<1, 1, 3><<<gproj, 256>>>(queries /*unused*/, Wo_w, Wo_b, out);
}

// round 5
// speedup vs baseline: 4.4947x; 1.0370x over previous
#include <cuda_runtime.h>
#include <math.h>

#define Bdim 4
#define Ldim 1024
#define Hdim 16
#define Ddim 64
#define HIDdim 1024
#define BHdim (Bdim*Hdim)

// Scratch intermediates (allocation-free rule: __device__ globals)
__device__ float g_q[BHdim*Ldim*Ddim];
__device__ float g_k[BHdim*Ldim*Ddim];
__device__ float g_v[BHdim*Ldim*Ddim];   // stored TRANSPOSED: [BH][D][L]
__device__ float g_att[BHdim*Ldim*Ddim]; // [BH][L][D]

__device__ __forceinline__ unsigned f2tf32(float x) {
    unsigned r;
    asm("cvt.rna.tf32.f32 %0, %1;" : "=r"(r) : "f"(x));
    return r;
}

__device__ __forceinline__ void mma_tf32(
    float& c0, float& c1, float& c2, float& c3,
    unsigned a0, unsigned a1, unsigned a2, unsigned a3,
    unsigned b0, unsigned b1)
{
    asm volatile(
        "mma.sync.aligned.m16n8k8.row.col.f32.tf32.tf32.f32 "
        "{%0,%1,%2,%3}, {%4,%5,%6,%7}, {%8,%9}, {%0,%1,%2,%3};"
        : "+f"(c0), "+f"(c1), "+f"(c2), "+f"(c3)
        : "r"(a0), "r"(a1), "r"(a2), "r"(a3), "r"(b0), "r"(b1));
}

__device__ __forceinline__ void cp16(void* smem, const void* gmem) {
    unsigned sa = (unsigned)__cvta_generic_to_shared(smem);
    asm volatile("cp.async.cg.shared.global [%0], [%1], 16;" :: "r"(sa), "l"(gmem));
}
#define CP_COMMIT() asm volatile("cp.async.commit_group;")
#define CP_WAIT0()  asm volatile("cp.async.wait_group 0;")
#define CP_WAIT1()  asm volatile("cp.async.wait_group 1;")

// ---------------------------------------------------------------------------
// Tensor-core GEMM, cp.async double-buffered: C[M,N] = A @ W^T + bias, K=1024
//   AMODE 0: A row-major [M,1024]; AMODE 1: A gathered from g_att head-split
//   CMODE 0: split-head store to g_q/g_k (DST 0/1); CMODE 1: plain store;
//   CMODE 2: transposed-V store (M=1024 hid dims, N=4096 tokens, bias by ROW)
// Block tile 128x128x32, 256 threads (8 warps 2m x 4n), warp tile 64x32.
// smem: fp32 staged (cvt to tf32 at fragment read -> same rna rounding).
// ---------------------------------------------------------------------------
#define GEMM_SMEM (2 * 2 * 128 * 36 * 4)

template<int AMODE, int CMODE, int DST>
__global__ void __launch_bounds__(256) gemm_tc(
    const float* __restrict__ A,
    const float* __restrict__ W,
    const float* __restrict__ bias,
    float* __restrict__ Cout)
{
    extern __shared__ float smf[];
    float* As = smf;                 // [2][128][36]
    float* Ws = smf + 2 * 128 * 36;  // [2][128][36]

    const int M0 = blockIdx.y * 128;
    const int N0 = blockIdx.x * 128;
    const int tid = threadIdx.x;
    const int wid = tid >> 5;
    const int lane = tid & 31;
    const int grp = lane >> 2;
    const int tig = lane & 3;
    const int wm = wid >> 2;
    const int wn = wid & 3;

    float c[4][4][4];
    #pragma unroll
    for (int mi = 0; mi < 4; mi++)
        #pragma unroll
        for (int ni = 0; ni < 4; ni++)
            #pragma unroll
            for (int r = 0; r < 4; r++) c[mi][ni][r] = 0.f;

    // issue stage loads for k-tile kt into buffer s
    auto issue = [&](int kt, int s) {
        const int k0 = kt * 32;
        #pragma unroll
        for (int p = 0; p < 4; p++) {
            const int cid = tid + p * 256;
            const int m = cid >> 3;
            const int cc = (cid & 7) << 2;
            const float* srcA;
            if (AMODE == 0) {
                srcA = A + (size_t)(M0 + m) * 1024 + k0 + cc;
            } else {
                const int gm = M0 + m;
                const int bi = gm >> 10, l = gm & 1023;
                const int kk = k0 + cc;
                const int h = kk >> 6, d = kk & 63;
                srcA = g_att + (((size_t)(bi * Hdim + h)) * Ldim + l) * Ddim + d;
            }
            cp16(&As[((size_t)s * 128 + m) * 36 + cc], srcA);
            cp16(&Ws[((size_t)s * 128 + m) * 36 + cc],
                 W + (size_t)(N0 + m) * 1024 + k0 + cc);
        }
        CP_COMMIT();
    };

    issue(0, 0);
    for (int kt = 0; kt < 32; kt++) {
        const int s = kt & 1;
        if (kt + 1 < 32) { issue(kt + 1, s ^ 1); CP_WAIT1(); }
        else             { CP_WAIT0(); }
        __syncthreads();

        const float* as = As + (size_t)s * 128 * 36;
        const float* ws = Ws + (size_t)s * 128 * 36;
        #pragma unroll
        for (int ks = 0; ks < 4; ks++) {
            const int kk = ks * 8;
            unsigned af[4][4], bf[4][2];
            #pragma unroll
            for (int mi = 0; mi < 4; mi++) {
                const int r = wm * 64 + mi * 16 + grp;
                af[mi][0] = f2tf32(as[r * 36 + kk + tig]);
                af[mi][1] = f2tf32(as[(r + 8) * 36 + kk + tig]);
                af[mi][2] = f2tf32(as[r * 36 + kk + tig + 4]);
                af[mi][3] = f2tf32(as[(r + 8) * 36 + kk + tig + 4]);
            }
            #pragma unroll
            for (int ni = 0; ni < 4; ni++) {
                const int n = wn * 32 + ni * 8 + grp;
                bf[ni][0] = f2tf32(ws[n * 36 + kk + tig]);
                bf[ni][1] = f2tf32(ws[n * 36 + kk + tig + 4]);
            }
            #pragma unroll
            for (int mi = 0; mi < 4; mi++)
                #pragma unroll
                for (int ni = 0; ni < 4; ni++)
                    mma_tf32(c[mi][ni][0], c[mi][ni][1], c[mi][ni][2], c[mi][ni][3],
                             af[mi][0], af[mi][1], af[mi][2], af[mi][3],
                             bf[ni][0], bf[ni][1]);
        }
        __syncthreads();
    }

    #pragma unroll
    for (int mi = 0; mi < 4; mi++) {
        #pragma unroll
        for (int ni = 0; ni < 4; ni++) {
            const int r0 = M0 + wm * 64 + mi * 16 + grp;
            const int r1 = r0 + 8;
            const int cn = N0 + wn * 32 + ni * 8 + tig * 2;
            if (CMODE == 2) {
                const float bv0 = bias[r0], bv1 = bias[r1];
                float2 v0 = make_float2(c[mi][ni][0] + bv0, c[mi][ni][1] + bv0);
                float2 v1 = make_float2(c[mi][ni][2] + bv1, c[mi][ni][3] + bv1);
                const size_t base = (size_t)(cn >> 10) * 1048576 + (cn & 1023);
                *(float2*)(g_v + base + (size_t)r0 * 1024) = v0;
                *(float2*)(g_v + base + (size_t)r1 * 1024) = v1;
            } else {
                const float bv0 = bias[cn], bv1 = bias[cn + 1];
                float2 v0 = make_float2(c[mi][ni][0] + bv0, c[mi][ni][1] + bv1);
                float2 v1 = make_float2(c[mi][ni][2] + bv0, c[mi][ni][3] + bv1);
                if (CMODE == 1) {
                    *(float2*)(Cout + (size_t)r0 * 1024 + cn) = v0;
                    *(float2*)(Cout + (size_t)r1 * 1024 + cn) = v1;
                } else {
                    float* dst = (DST == 0) ? g_q : g_k;
                    const int h = cn >> 6, d = cn & 63;
                    const int bi0 = r0 >> 10, l0 = r0 & 1023;
                    const int bi1 = r1 >> 10, l1 = r1 & 1023;
                    *(float2*)(dst + (((size_t)(bi0 * Hdim + h)) * Ldim + l0) * Ddim + d) = v0;
                    *(float2*)(dst + (((size_t)(bi1 * Hdim + h)) * Ldim + l1) * Ddim + d) = v1;
                }
            }
        }
    }
}

// ---------------------------------------------------------------------------
// Fused flash attention: per block = 128 query rows of one head.
// Per 64-key tile: prefetch prev (cp.async, warp-local rows, overlaps S mma)
// -> S = Q@K^T (mma) -> blend with prev from smem (write scores) -> mask+scale
// -> online softmax -> P (tf32, overwrites prev slots) -> O += P@V (mma).
// smem: uQ[128][68], uK[64][68], uV[64][68] (V^T tile), uP[128][68] (prev/P).
// ---------------------------------------------------------------------------
#define SMEM_FUSED ((128*68 + 64*68 + 64*68 + 128*68) * 4)

__global__ void __launch_bounds__(256, 2) fused_attn(
    const float* __restrict__ prev,
    const int* __restrict__ mask,
    const float* __restrict__ gat,
    float* __restrict__ scores)
{
    extern __shared__ unsigned sm[];
    unsigned* uQ = sm;                   // [128][68]
    unsigned* uK = uQ + 128 * 68;        // [64][68]   K tile [j][d]
    unsigned* uV = uK + 64 * 68;         // [64][68]   V^T tile [d][j]
    unsigned* uP = uV + 64 * 68;         // [128][68]  prev staging / P tile
    float* fP = (float*)uP;

    const int bh = blockIdx.y;
    const int q0 = blockIdx.x * 128;
    const int tid = threadIdx.x;
    const int w = tid >> 5;
    const int lane = tid & 31;
    const int grp = lane >> 2;
    const int tig = lane & 3;
    const int rw0 = w * 16 + grp;
    const int rw1 = rw0 + 8;
    const int gq0 = q0 + rw0;
    const int gq1 = q0 + rw1;

    const float* qg = g_q + (size_t)bh * Ldim * Ddim;
    const float* kg = g_k + (size_t)bh * Ldim * Ddim;
    const float* vg = g_v + (size_t)bh * Ddim * Ldim;   // transposed [d][l]
    const size_t sb = ((size_t)bh << 20);
    const float* prevb = prev + sb + (size_t)(q0 + w * 16) * Ldim;

    // Load Q tile once (128 x 64)
    #pragma unroll
    for (int p = 0; p < 8; p++) {
        const int idx = tid + p * 256;
        const int m = idx >> 4;
        const int cc = (idx & 15) << 2;
        const float4 va = *(const float4*)(qg + (size_t)(q0 + m) * Ddim + cc);
        unsigned ua[4] = { f2tf32(va.x), f2tf32(va.y), f2tf32(va.z), f2tf32(va.w) };
        *(uint4*)&uQ[m * 68 + cc] = *(uint4*)ua;
    }

    const int vl0 = mask[(bh & 3) * Ldim + gq0];
    const int vl1 = mask[(bh & 3) * Ldim + gq1];
    const float gv = 1.f / (1.f + __expf(-gat[0]));
    const float og = 1.f - gv;

    float o[8][4];
    #pragma unroll
    for (int ni = 0; ni < 8; ni++)
        #pragma unroll
        for (int r = 0; r < 4; r++) o[ni][r] = 0.f;
    float mi0 = -1e30f, mi1 = -1e30f, li0 = 0.f, li1 = 0.f;

    for (int kt = 0; kt < Ldim; kt += 64) {
        // 1) Prefetch prev tile rows owned by this warp (16 rows x 64 cols).
        //    uP is free here: PV mma of previous tile consumed it pre-sync.
        #pragma unroll
        for (int j = 0; j < 8; j++) {
            const int cid = j * 32 + lane;       // 0..255
            const int r = cid >> 4;              // 0..15 (warp-local row)
            const int c4 = (cid & 15) << 2;      // 0..60
            cp16(&uP[(w * 16 + r) * 68 + c4],
                 prevb + (size_t)r * Ldim + kt + c4);
        }
        CP_COMMIT();

        // 2) Load K tile [j][d] and V^T tile [d][j] (both 64x64, coalesced)
        #pragma unroll
        for (int p = 0; p < 4; p++) {
            const int idx = tid + p * 256;
            const int r = idx >> 4;
            const int cc = (idx & 15) << 2;
            const float4 vk = *(const float4*)(kg + (size_t)(kt + r) * Ddim + cc);
            unsigned uk[4] = { f2tf32(vk.x), f2tf32(vk.y), f2tf32(vk.z), f2tf32(vk.w) };
            *(uint4*)&uK[r * 68 + cc] = *(uint4*)uk;
            const float4 vv = *(const float4*)(vg + (size_t)r * Ldim + kt + cc);
            unsigned uv[4] = { f2tf32(vv.x), f2tf32(vv.y), f2tf32(vv.z), f2tf32(vv.w) };
            *(uint4*)&uV[r * 68 + cc] = *(uint4*)uv;
        }
        __syncthreads();

        // 3) S = Q @ K^T : warp computes 16 rows x 64 cols (prev cp.async in flight)
        float cs[8][4];
        #pragma unroll
        for (int ni = 0; ni < 8; ni++)
            #pragma unroll
            for (int r = 0; r < 4; r++) cs[ni][r] = 0.f;

        #pragma unroll
        for (int ks = 0; ks < 8; ks++) {
            const int kk = ks * 8;
            const unsigned a0 = uQ[rw0 * 68 + kk + tig];
            const unsigned a1 = uQ[rw1 * 68 + kk + tig];
            const unsigned a2 = uQ[rw0 * 68 + kk + tig + 4];
            const unsigned a3 = uQ[rw1 * 68 + kk + tig + 4];
            #pragma unroll
            for (int ni = 0; ni < 8; ni++) {
                const unsigned b0 = uK[(ni * 8 + grp) * 68 + kk + tig];
                const unsigned b1 = uK[(ni * 8 + grp) * 68 + kk + tig + 4];
                mma_tf32(cs[ni][0], cs[ni][1], cs[ni][2], cs[ni][3],
                         a0, a1, a2, a3, b0, b1);
            }
        }

        // 4) prev landed (warp-local): blend, write scores, mask+scale
        CP_WAIT0();
        __syncwarp();

        float m0 = -1e30f, m1 = -1e30f;
        #pragma unroll
        for (int ni = 0; ni < 8; ni++) {
            const int cl = ni * 8 + tig * 2;
            const int col = kt + cl;
            const float2 p0 = *(const float2*)&fP[rw0 * 68 + cl];
            const float2 p1 = *(const float2*)&fP[rw1 * 68 + cl];
            const float b00 = p0.x * gv + og * cs[ni][0];
            const float b01 = p0.y * gv + og * cs[ni][1];
            const float b10 = p1.x * gv + og * cs[ni][2];
            const float b11 = p1.y * gv + og * cs[ni][3];
            const size_t i0 = sb + (size_t)gq0 * Ldim + col;
            const size_t i1 = sb + (size_t)gq1 * Ldim + col;
            *(float2*)(scores + i0) = make_float2(b00, b01);
            *(float2*)(scores + i1) = make_float2(b10, b11);
            cs[ni][0] = (col     < vl0) ? b00 * 0.125f : -1e30f;
            cs[ni][1] = (col + 1 < vl0) ? b01 * 0.125f : -1e30f;
            cs[ni][2] = (col     < vl1) ? b10 * 0.125f : -1e30f;
            cs[ni][3] = (col + 1 < vl1) ? b11 * 0.125f : -1e30f;
            m0 = fmaxf(m0, fmaxf(cs[ni][0], cs[ni][1]));
            m1 = fmaxf(m1, fmaxf(cs[ni][2], cs[ni][3]));
        }
        m0 = fmaxf(m0, __shfl_xor_sync(0xffffffffu, m0, 1));
        m0 = fmaxf(m0, __shfl_xor_sync(0xffffffffu, m0, 2));
        m1 = fmaxf(m1, __shfl_xor_sync(0xffffffffu, m1, 1));
        m1 = fmaxf(m1, __shfl_xor_sync(0xffffffffu, m1, 2));

        const float mn0 = fmaxf(mi0, m0);
        const float mn1 = fmaxf(mi1, m1);
        const float cr0 = __expf(mi0 - mn0);
        const float cr1 = __expf(mi1 - mn1);
        li0 *= cr0; li1 *= cr1;
        #pragma unroll
        for (int ni = 0; ni < 8; ni++) {
            o[ni][0] *= cr0; o[ni][1] *= cr0;
            o[ni][2] *= cr1; o[ni][3] *= cr1;
        }
        mi0 = mn0; mi1 = mn1;

        // 5) P = exp(s - m), row sums, store tf32 into uP (overwriting prev)
        #pragma unroll
        for (int ni = 0; ni < 8; ni++) {
            const float p00 = __expf(cs[ni][0] - mn0);
            const float p01 = __expf(cs[ni][1] - mn0);
            const float p10 = __expf(cs[ni][2] - mn1);
            const float p11 = __expf(cs[ni][3] - mn1);
            li0 += p00 + p01;
            li1 += p10 + p11;
            const int pc = ni * 8 + tig * 2;
            uP[rw0 * 68 + pc]     = f2tf32(p00);
            uP[rw0 * 68 + pc + 1] = f2tf32(p01);
            uP[rw1 * 68 + pc]     = f2tf32(p10);
            uP[rw1 * 68 + pc + 1] = f2tf32(p11);
        }
        __syncwarp();

        // 6) O += P @ V
        #pragma unroll
        for (int ks = 0; ks < 8; ks++) {
            const int kk = ks * 8;
            const unsigned a0 = uP[rw0 * 68 + kk + tig];
            const unsigned a1 = uP[rw1 * 68 + kk + tig];
            const unsigned a2 = uP[rw0 * 68 + kk + tig + 4];
            const unsigned a3 = uP[rw1 * 68 + kk + tig + 4];
            #pragma unroll
            for (int ni = 0; ni < 8; ni++) {
                const unsigned b0 = uV[(ni * 8 + grp) * 68 + kk + tig];
                const unsigned b1 = uV[(ni * 8 + grp) * 68 + kk + tig + 4];
                mma_tf32(o[ni][0], o[ni][1], o[ni][2], o[ni][3],
                         a0, a1, a2, a3, b0, b1);
            }
        }
        __syncthreads();
    }

    // Final: normalize by row sums and write att
    li0 += __shfl_xor_sync(0xffffffffu, li0, 1);
    li0 += __shfl_xor_sync(0xffffffffu, li0, 2);
    li1 += __shfl_xor_sync(0xffffffffu, li1, 1);
    li1 += __shfl_xor_sync(0xffffffffu, li1, 2);
    const float inv0 = 1.f / li0;
    const float inv1 = 1.f / li1;

    float* ab = g_att + (size_t)bh * Ldim * Ddim;
    #pragma unroll
    for (int ni = 0; ni < 8; ni++) {
        const int d = ni * 8 + tig * 2;
        *(float2*)(ab + (size_t)gq0 * Ddim + d) =
            make_float2(o[ni][0] * inv0, o[ni][1] * inv0);
        *(float2*)(ab + (size_t)gq1 * Ddim + d) =
            make_float2(o[ni][2] * inv1, o[ni][3] * inv1);
    }
}

// ---------------------------------------------------------------------------
// Launch.  Inputs: queries, keys, values, prev, mask(int32),
//   Wq_w, Wq_b, Wk_w, Wk_b, Wv_w, Wv_b, Wo_w, Wo_b, gat
// Output: [out (4M floats) | scores (64M floats)]
// ---------------------------------------------------------------------------
extern "C" void kernel_launch(void* const* d_in, const int* in_sizes, int n_in,
                              void* d_out, int out_size)
{
    (void)in_sizes; (void)n_in; (void)out_size;
    const float* queries = (const float*)d_in[0];
    const float* keys    = (const float*)d_in[1];
    const float* values  = (const float*)d_in[2];
    const float* prev    = (const float*)d_in[3];
    const int*   mask    = (const int*)d_in[4];
    const float* Wq_w = (const float*)d_in[5];
    const float* Wq_b = (const float*)d_in[6];
    const float* Wk_w = (const float*)d_in[7];
    const float* Wk_b = (const float*)d_in[8];
    const float* Wv_w = (const float*)d_in[9];
    const float* Wv_b = (const float*)d_in[10];
    const float* Wo_w = (const float*)d_in[11];
    const float* Wo_b = (const float*)d_in[12];
    const float* gat  = (const float*)d_in[13];

    float* out    = (float*)d_out;
    float* scores = out + (size_t)Bdim * Ldim * HIDdim;

    cudaFuncSetAttribute(fused_attn,
                         cudaFuncAttributeMaxDynamicSharedMemorySize, SMEM_FUSED);
    cudaFuncSetAttribute(gemm_tc<0,0,0>,
                         cudaFuncAttributeMaxDynamicSharedMemorySize, GEMM_SMEM);
    cudaFuncSetAttribute(gemm_tc<0,0,1>,
                         cudaFuncAttributeMaxDynamicSharedMemorySize, GEMM_SMEM);
    cudaFuncSetAttribute(gemm_tc<0,2,2>,
                         cudaFuncAttributeMaxDynamicSharedMemorySize, GEMM_SMEM);
    cudaFuncSetAttribute(gemm_tc<1,1,3>,
                         cudaFuncAttributeMaxDynamicSharedMemorySize, GEMM_SMEM);

    dim3 gproj(8, 32);
    gemm_tc<0, 0, 0><<<gproj, 256, GEMM_SMEM>>>(queries, Wq_w, Wq_b, nullptr);
    gemm_tc<0, 0, 1><<<gproj, 256, GEMM_SMEM>>>(keys,    Wk_w, Wk_b, nullptr);
    // V projection computed transposed: C^T = Wv @ values^T
    dim3 gvt(32, 8);
    gemm_tc<0, 2, 2><<<gvt, 256, GEMM_SMEM>>>(Wv_w, values, Wv_b, nullptr);

    dim3 gf(8, 64);
    fused_attn<<<gf, 256, SMEM_FUSED>>>(prev, mask, gat, scores);

    gemm_tc<1, 1, 3><<<gproj, 256, GEMM_SMEM>>>(queries /*unused*/, Wo_w, Wo_b, out);
}

// round 6
// speedup vs baseline: 4.6853x; 1.0424x over previous
#include <cuda_runtime.h>
#include <math.h>

#define Bdim 4
#define Ldim 1024
#define Hdim 16
#define Ddim 64
#define HIDdim 1024
#define BHdim (Bdim*Hdim)

// Scratch intermediates (allocation-free rule: __device__ globals)
__device__ float g_q[BHdim*Ldim*Ddim];
__device__ float g_k[BHdim*Ldim*Ddim];
__device__ float g_v[BHdim*Ldim*Ddim];   // stored TRANSPOSED: [BH][D][L]
__device__ float g_att[BHdim*Ldim*Ddim]; // [BH][L][D]

__device__ __forceinline__ unsigned f2tf32(float x) {
    unsigned r;
    asm("cvt.rna.tf32.f32 %0, %1;" : "=r"(r) : "f"(x));
    return r;
}

__device__ __forceinline__ void mma_tf32(
    float& c0, float& c1, float& c2, float& c3,
    unsigned a0, unsigned a1, unsigned a2, unsigned a3,
    unsigned b0, unsigned b1)
{
    asm volatile(
        "mma.sync.aligned.m16n8k8.row.col.f32.tf32.tf32.f32 "
        "{%0,%1,%2,%3}, {%4,%5,%6,%7}, {%8,%9}, {%0,%1,%2,%3};"
        : "+f"(c0), "+f"(c1), "+f"(c2), "+f"(c3)
        : "r"(a0), "r"(a1), "r"(a2), "r"(a3), "r"(b0), "r"(b1));
}

__device__ __forceinline__ void cp16(void* smem, const void* gmem) {
    unsigned sa = (unsigned)__cvta_generic_to_shared(smem);
    asm volatile("cp.async.cg.shared.global [%0], [%1], 16;" :: "r"(sa), "l"(gmem));
}
#define CP_COMMIT() asm volatile("cp.async.commit_group;")
#define CP_WAIT0()  asm volatile("cp.async.wait_group 0;")
#define CP_WAIT1()  asm volatile("cp.async.wait_group 1;")

#define GEMM_SMEM (2 * 2 * 128 * 36 * 4)

// ---------------------------------------------------------------------------
// GEMM core (cp.async double-buffered k-pipeline), shared by QKV + O kernels.
// Computes a 128x128 tile of A[M0..] @ W[N0..]^T, both row-major K=1024.
// Result in c[4][4][4] per thread (8 warps 2m x 4n, warp tile 64x32).
// ---------------------------------------------------------------------------
struct GemmCore {
    float c[4][4][4];

    template<class SrcA>
    __device__ __forceinline__ void run(
        float* smf, SrcA srcA, const float* __restrict__ W,
        int M0, int N0, int tid, int wm, int wn, int grp, int tig)
    {
        float* As = smf;
        float* Ws = smf + 2 * 128 * 36;
        #pragma unroll
        for (int mi = 0; mi < 4; mi++)
            #pragma unroll
            for (int ni = 0; ni < 4; ni++)
                #pragma unroll
                for (int r = 0; r < 4; r++) c[mi][ni][r] = 0.f;

        auto issue = [&](int kt, int s) {
            const int k0 = kt * 32;
            #pragma unroll
            for (int p = 0; p < 4; p++) {
                const int cid = tid + p * 256;
                const int m = cid >> 3;
                const int cc = (cid & 7) << 2;
                cp16(&As[((size_t)s * 128 + m) * 36 + cc], srcA(M0 + m, k0 + cc));
                cp16(&Ws[((size_t)s * 128 + m) * 36 + cc],
                     W + (size_t)(N0 + m) * 1024 + k0 + cc);
            }
            CP_COMMIT();
        };

        issue(0, 0);
        for (int kt = 0; kt < 32; kt++) {
            const int s = kt & 1;
            if (kt + 1 < 32) { issue(kt + 1, s ^ 1); CP_WAIT1(); }
            else             { CP_WAIT0(); }
            __syncthreads();

            const float* as = As + (size_t)s * 128 * 36;
            const float* ws = Ws + (size_t)s * 128 * 36;
            #pragma unroll
            for (int ks = 0; ks < 4; ks++) {
                const int kk = ks * 8;
                unsigned af[4][4], bf[4][2];
                #pragma unroll
                for (int mi = 0; mi < 4; mi++) {
                    const int r = wm * 64 + mi * 16 + grp;
                    af[mi][0] = f2tf32(as[r * 36 + kk + tig]);
                    af[mi][1] = f2tf32(as[(r + 8) * 36 + kk + tig]);
                    af[mi][2] = f2tf32(as[r * 36 + kk + tig + 4]);
                    af[mi][3] = f2tf32(as[(r + 8) * 36 + kk + tig + 4]);
                }
                #pragma unroll
                for (int ni = 0; ni < 4; ni++) {
                    const int n = wn * 32 + ni * 8 + grp;
                    bf[ni][0] = f2tf32(ws[n * 36 + kk + tig]);
                    bf[ni][1] = f2tf32(ws[n * 36 + kk + tig + 4]);
                }
                #pragma unroll
                for (int mi = 0; mi < 4; mi++)
                    #pragma unroll
                    for (int ni = 0; ni < 4; ni++)
                        mma_tf32(c[mi][ni][0], c[mi][ni][1], c[mi][ni][2], c[mi][ni][3],
                                 af[mi][0], af[mi][1], af[mi][2], af[mi][3],
                                 bf[ni][0], bf[ni][1]);
            }
            __syncthreads();
        }
    }
};

// ---------------------------------------------------------------------------
// Merged Q/K/V projection: 768 blocks, z = blockIdx.x>>8 selects which GEMM.
//   z=0: g_q = queries @ Wq^T + bq (split-head store)
//   z=1: g_k = keys    @ Wk^T + bk (split-head store)
//   z=2: g_v^T = Wv @ values^T + bv (transposed store, bias by ROW)
// ---------------------------------------------------------------------------
__global__ void __launch_bounds__(256) qkv_gemm(
    const float* __restrict__ queries, const float* __restrict__ keys,
    const float* __restrict__ values,
    const float* __restrict__ Wq_w, const float* __restrict__ Wq_b,
    const float* __restrict__ Wk_w, const float* __restrict__ Wk_b,
    const float* __restrict__ Wv_w, const float* __restrict__ Wv_b)
{
    extern __shared__ float smf[];
    const int g = blockIdx.x;
    const int z = g >> 8;
    const int r = g & 255;
    const int tid = threadIdx.x;
    const int wid = tid >> 5;
    const int lane = tid & 31;
    const int grp = lane >> 2;
    const int tig = lane & 3;
    const int wm = wid >> 2;
    const int wn = wid & 3;

    const float *A, *W, *bias;
    int M0, N0;
    if (z == 0)      { A = queries; W = Wq_w; bias = Wq_b; M0 = (r >> 3) * 128; N0 = (r & 7) * 128; }
    else if (z == 1) { A = keys;    W = Wk_w; bias = Wk_b; M0 = (r >> 3) * 128; N0 = (r & 7) * 128; }
    else             { A = Wv_w;    W = values; bias = Wv_b; M0 = (r & 7) * 128; N0 = (r >> 3) * 128; }

    GemmCore gc;
    gc.run(smf, [&](int m, int k) { return A + (size_t)m * 1024 + k; },
           W, M0, N0, tid, wm, wn, grp, tig);

    #pragma unroll
    for (int mi = 0; mi < 4; mi++) {
        #pragma unroll
        for (int ni = 0; ni < 4; ni++) {
            const int r0 = M0 + wm * 64 + mi * 16 + grp;
            const int r1 = r0 + 8;
            const int cn = N0 + wn * 32 + ni * 8 + tig * 2;
            if (z == 2) {
                const float bv0 = bias[r0], bv1 = bias[r1];
                float2 v0 = make_float2(gc.c[mi][ni][0] + bv0, gc.c[mi][ni][1] + bv0);
                float2 v1 = make_float2(gc.c[mi][ni][2] + bv1, gc.c[mi][ni][3] + bv1);
                const size_t base = (size_t)(cn >> 10) * 1048576 + (cn & 1023);
                *(float2*)(g_v + base + (size_t)r0 * 1024) = v0;
                *(float2*)(g_v + base + (size_t)r1 * 1024) = v1;
            } else {
                float* dst = (z == 0) ? g_q : g_k;
                const float bv0 = bias[cn], bv1 = bias[cn + 1];
                float2 v0 = make_float2(gc.c[mi][ni][0] + bv0, gc.c[mi][ni][1] + bv1);
                float2 v1 = make_float2(gc.c[mi][ni][2] + bv0, gc.c[mi][ni][3] + bv1);
                const int h = cn >> 6, d = cn & 63;
                const int bi0 = r0 >> 10, l0 = r0 & 1023;
                const int bi1 = r1 >> 10, l1 = r1 & 1023;
                *(float2*)(dst + (((size_t)(bi0 * Hdim + h)) * Ldim + l0) * Ddim + d) = v0;
                *(float2*)(dst + (((size_t)(bi1 * Hdim + h)) * Ldim + l1) * Ddim + d) = v1;
            }
        }
    }
}

// ---------------------------------------------------------------------------
// Output projection: out = merge_heads(g_att) @ Wo^T + bo
// ---------------------------------------------------------------------------
__global__ void __launch_bounds__(256) out_gemm(
    const float* __restrict__ W,
    const float* __restrict__ bias,
    float* __restrict__ Cout)
{
    extern __shared__ float smf[];
    const int M0 = blockIdx.y * 128;
    const int N0 = blockIdx.x * 128;
    const int tid = threadIdx.x;
    const int wid = tid >> 5;
    const int lane = tid & 31;
    const int grp = lane >> 2;
    const int tig = lane & 3;
    const int wm = wid >> 2;
    const int wn = wid & 3;

    GemmCore gc;
    gc.run(smf,
        [&](int m, int k) {
            const int bi = m >> 10, l = m & 1023;
            const int h = k >> 6, d = k & 63;
            return (const float*)(g_att + (((size_t)(bi * Hdim + h)) * Ldim + l) * Ddim + d);
        },
        W, M0, N0, tid, wm, wn, grp, tig);

    #pragma unroll
    for (int mi = 0; mi < 4; mi++) {
        #pragma unroll
        for (int ni = 0; ni < 4; ni++) {
            const int r0 = M0 + wm * 64 + mi * 16 + grp;
            const int r1 = r0 + 8;
            const int cn = N0 + wn * 32 + ni * 8 + tig * 2;
            const float bv0 = bias[cn], bv1 = bias[cn + 1];
            *(float2*)(Cout + (size_t)r0 * 1024 + cn) =
                make_float2(gc.c[mi][ni][0] + bv0, gc.c[mi][ni][1] + bv1);
            *(float2*)(Cout + (size_t)r1 * 1024 + cn) =
                make_float2(gc.c[mi][ni][2] + bv0, gc.c[mi][ni][3] + bv1);
        }
    }
}

// ---------------------------------------------------------------------------
// Fused flash attention, cp.async software-pipelined.
// Per 64-key tile t:
//   wait K[t] -> S=Q@K^T (mma) -> sync -> issue K[t+1]
//   wait {V,prev}[t] -> blend prev (write scores) -> mask -> online softmax
//   -> P (tf32) -> sync -> O += P@V (mma) -> sync -> issue {V,prev}[t+1]
// Group pending order is always [K, {V,prev}]: wait_group 1 at each point.
// smem: uQ tf32[128][68], fK fp32[64][68], fV fp32[64][68], uP[128][68].
// ---------------------------------------------------------------------------
#define SMEM_FUSED ((128*68 + 64*68 + 64*68 + 128*68) * 4)

__global__ void __launch_bounds__(256, 2) fused_attn(
    const float* __restrict__ prev,
    const int* __restrict__ mask,
    const float* __restrict__ gat,
    float* __restrict__ scores)
{
    extern __shared__ unsigned sm[];
    unsigned* uQ = sm;                   // [128][68] tf32
    float* fK = (float*)(uQ + 128 * 68); // [64][68]  K tile [j][d], raw fp32
    float* fV = fK + 64 * 68;            // [64][68]  V^T tile [d][j], raw fp32
    unsigned* uP = (unsigned*)(fV + 64 * 68); // [128][68] prev fp32 / P tf32
    float* fP = (float*)uP;

    const int bh = blockIdx.y;
    const int q0 = blockIdx.x * 128;
    const int tid = threadIdx.x;
    const int w = tid >> 5;
    const int lane = tid & 31;
    const int grp = lane >> 2;
    const int tig = lane & 3;
    const int rw0 = w * 16 + grp;
    const int rw1 = rw0 + 8;
    const int gq0 = q0 + rw0;
    const int gq1 = q0 + rw1;

    const float* qg = g_q + (size_t)bh * Ldim * Ddim;
    const float* kg = g_k + (size_t)bh * Ldim * Ddim;
    const float* vg = g_v + (size_t)bh * Ddim * Ldim;   // transposed [d][l]
    const size_t sb = ((size_t)bh << 20);
    const float* prevb = prev + sb + (size_t)(q0 + w * 16) * Ldim;

    // issue helpers -------------------------------------------------------
    auto issueK = [&](int kt) {
        #pragma unroll
        for (int p = 0; p < 4; p++) {
            const int idx = tid + p * 256;
            const int r = idx >> 4;
            const int cc = (idx & 15) << 2;
            cp16(&fK[r * 68 + cc], kg + (size_t)(kt + r) * Ddim + cc);
        }
        CP_COMMIT();
    };
    auto issueVP = [&](int kt) {
        #pragma unroll
        for (int p = 0; p < 4; p++) {
            const int idx = tid + p * 256;
            const int r = idx >> 4;
            const int cc = (idx & 15) << 2;
            cp16(&fV[r * 68 + cc], vg + (size_t)r * Ldim + kt + cc);
        }
        #pragma unroll
        for (int j = 0; j < 8; j++) {
            const int cid = j * 32 + lane;
            const int r = cid >> 4;
            const int c4 = (cid & 15) << 2;
            cp16(&uP[(w * 16 + r) * 68 + c4], prevb + (size_t)r * Ldim + c4);
        }
        CP_COMMIT();
    };
    auto issueVP_t = [&](int kt) {
        #pragma unroll
        for (int p = 0; p < 4; p++) {
            const int idx = tid + p * 256;
            const int r = idx >> 4;
            const int cc = (idx & 15) << 2;
            cp16(&fV[r * 68 + cc], vg + (size_t)r * Ldim + kt + cc);
        }
        #pragma unroll
        for (int j = 0; j < 8; j++) {
            const int cid = j * 32 + lane;
            const int r = cid >> 4;
            const int c4 = (cid & 15) << 2;
            cp16(&uP[(w * 16 + r) * 68 + c4], prevb + (size_t)r * Ldim + kt + c4);
        }
        CP_COMMIT();
    };

    // prologue: K[0] group first, then {V,prev}[0]
    issueK(0);
    issueVP(0);

    // Load Q tile once (128 x 64), convert to tf32
    #pragma unroll
    for (int p = 0; p < 8; p++) {
        const int idx = tid + p * 256;
        const int m = idx >> 4;
        const int cc = (idx & 15) << 2;
        const float4 va = *(const float4*)(qg + (size_t)(q0 + m) * Ddim + cc);
        unsigned ua[4] = { f2tf32(va.x), f2tf32(va.y), f2tf32(va.z), f2tf32(va.w) };
        *(uint4*)&uQ[m * 68 + cc] = *(uint4*)ua;
    }

    const int vl0 = mask[(bh & 3) * Ldim + gq0];
    const int vl1 = mask[(bh & 3) * Ldim + gq1];
    const float gv = 1.f / (1.f + __expf(-gat[0]));
    const float og = 1.f - gv;

    float o[8][4];
    #pragma unroll
    for (int ni = 0; ni < 8; ni++)
        #pragma unroll
        for (int r = 0; r < 4; r++) o[ni][r] = 0.f;
    float mi0 = -1e30f, mi1 = -1e30f, li0 = 0.f, li1 = 0.f;

    for (int kt = 0; kt < Ldim; kt += 64) {
        const bool more = (kt + 64 < Ldim);

        // pending: [K[t], {V,prev}[t]] -> wait K
        CP_WAIT1();
        __syncthreads();

        // S = Q @ K^T (K raw fp32 -> cvt at read)
        float cs[8][4];
        #pragma unroll
        for (int ni = 0; ni < 8; ni++)
            #pragma unroll
            for (int r = 0; r < 4; r++) cs[ni][r] = 0.f;

        #pragma unroll
        for (int ks = 0; ks < 8; ks++) {
            const int kk = ks * 8;
            const unsigned a0 = uQ[rw0 * 68 + kk + tig];
            const unsigned a1 = uQ[rw1 * 68 + kk + tig];
            const unsigned a2 = uQ[rw0 * 68 + kk + tig + 4];
            const unsigned a3 = uQ[rw1 * 68 + kk + tig + 4];
            #pragma unroll
            for (int ni = 0; ni < 8; ni++) {
                const unsigned b0 = f2tf32(fK[(ni * 8 + grp) * 68 + kk + tig]);
                const unsigned b1 = f2tf32(fK[(ni * 8 + grp) * 68 + kk + tig + 4]);
                mma_tf32(cs[ni][0], cs[ni][1], cs[ni][2], cs[ni][3],
                         a0, a1, a2, a3, b0, b1);
            }
        }
        __syncthreads();               // K buffer free
        if (more) issueK(kt + 64);     // overlaps epilogue + PV

        // wait {V,prev}[t] (K[t+1] may stay pending)
        if (more) CP_WAIT1(); else CP_WAIT0();
        __syncwarp();                  // prev rows are warp-local

        // blend with prev, write scores, mask+scale
        float m0 = -1e30f, m1 = -1e30f;
        #pragma unroll
        for (int ni = 0; ni < 8; ni++) {
            const int cl = ni * 8 + tig * 2;
            const int col = kt + cl;
            const float2 p0 = *(const float2*)&fP[rw0 * 68 + cl];
            const float2 p1 = *(const float2*)&fP[rw1 * 68 + cl];
            const float b00 = p0.x * gv + og * cs[ni][0];
            const float b01 = p0.y * gv + og * cs[ni][1];
            const float b10 = p1.x * gv + og * cs[ni][2];
            const float b11 = p1.y * gv + og * cs[ni][3];
            const size_t i0 = sb + (size_t)gq0 * Ldim + col;
            const size_t i1 = sb + (size_t)gq1 * Ldim + col;
            *(float2*)(scores + i0) = make_float2(b00, b01);
            *(float2*)(scores + i1) = make_float2(b10, b11);
            cs[ni][0] = (col     < vl0) ? b00 * 0.125f : -1e30f;
            cs[ni][1] = (col + 1 < vl0) ? b01 * 0.125f : -1e30f;
            cs[ni][2] = (col     < vl1) ? b10 * 0.125f : -1e30f;
            cs[ni][3] = (col + 1 < vl1) ? b11 * 0.125f : -1e30f;
            m0 = fmaxf(m0, fmaxf(cs[ni][0], cs[ni][1]));
            m1 = fmaxf(m1, fmaxf(cs[ni][2], cs[ni][3]));
        }
        m0 = fmaxf(m0, __shfl_xor_sync(0xffffffffu, m0, 1));
        m0 = fmaxf(m0, __shfl_xor_sync(0xffffffffu, m0, 2));
        m1 = fmaxf(m1, __shfl_xor_sync(0xffffffffu, m1, 1));
        m1 = fmaxf(m1, __shfl_xor_sync(0xffffffffu, m1, 2));

        const float mn0 = fmaxf(mi0, m0);
        const float mn1 = fmaxf(mi1, m1);
        const float cr0 = __expf(mi0 - mn0);
        const float cr1 = __expf(mi1 - mn1);
        li0 *= cr0; li1 *= cr1;
        #pragma unroll
        for (int ni = 0; ni < 8; ni++) {
            o[ni][0] *= cr0; o[ni][1] *= cr0;
            o[ni][2] *= cr1; o[ni][3] *= cr1;
        }
        mi0 = mn0; mi1 = mn1;

        // P = exp(s - m) -> tf32 into uP (overwrites prev slots, warp-local)
        #pragma unroll
        for (int ni = 0; ni < 8; ni++) {
            const float p00 = __expf(cs[ni][0] - mn0);
            const float p01 = __expf(cs[ni][1] - mn0);
            const float p10 = __expf(cs[ni][2] - mn1);
            const float p11 = __expf(cs[ni][3] - mn1);
            li0 += p00 + p01;
            li1 += p10 + p11;
            const int pc = ni * 8 + tig * 2;
            uP[rw0 * 68 + pc]     = f2tf32(p00);
            uP[rw0 * 68 + pc + 1] = f2tf32(p01);
            uP[rw1 * 68 + pc]     = f2tf32(p10);
            uP[rw1 * 68 + pc + 1] = f2tf32(p11);
        }
        __syncthreads();               // V visible block-wide; P ready

        // O += P @ V (V raw fp32 -> cvt at read)
        #pragma unroll
        for (int ks = 0; ks < 8; ks++) {
            const int kk = ks * 8;
            const unsigned a0 = uP[rw0 * 68 + kk + tig];
            const unsigned a1 = uP[rw1 * 68 + kk + tig];
            const unsigned a2 = uP[rw0 * 68 + kk + tig + 4];
            const unsigned a3 = uP[rw1 * 68 + kk + tig + 4];
            #pragma unroll
            for (int ni = 0; ni < 8; ni++) {
                const unsigned b0 = f2tf32(fV[(ni * 8 + grp) * 68 + kk + tig]);
                const unsigned b1 = f2tf32(fV[(ni * 8 + grp) * 68 + kk + tig + 4]);
                mma_tf32(o[ni][0], o[ni][1], o[ni][2], o[ni][3],
                         a0, a1, a2, a3, b0, b1);
            }
        }
        __syncthreads();               // V + uP buffers free
        if (more) issueVP_t(kt + 64);  // overlaps next tile's S mma
    }

    // Final: normalize by row sums and write att
    li0 += __shfl_xor_sync(0xffffffffu, li0, 1);
    li0 += __shfl_xor_sync(0xffffffffu, li0, 2);
    li1 += __shfl_xor_sync(0xffffffffu, li1, 1);
    li1 += __shfl_xor_sync(0xffffffffu, li1, 2);
    const float inv0 = 1.f / li0;
    const float inv1 = 1.f / li1;

    float* ab = g_att + (size_t)bh * Ldim * Ddim;
    #pragma unroll
    for (int ni = 0; ni < 8; ni++) {
        const int d = ni * 8 + tig * 2;
        *(float2*)(ab + (size_t)gq0 * Ddim + d) =
            make_float2(o[ni][0] * inv0, o[ni][1] * inv0);
        *(float2*)(ab + (size_t)gq1 * Ddim + d) =
            make_float2(o[ni][2] * inv1, o[ni][3] * inv1);
    }
}

// ---------------------------------------------------------------------------
// Launch.  Inputs: queries, keys, values, prev, mask(int32),
//   Wq_w, Wq_b, Wk_w, Wk_b, Wv_w, Wv_b, Wo_w, Wo_b, gat
// Output: [out (4M floats) | scores (64M floats)]
// ---------------------------------------------------------------------------
extern "C" void kernel_launch(void* const* d_in, const int* in_sizes, int n_in,
                              void* d_out, int out_size)
{
    (void)in_sizes; (void)n_in; (void)out_size;
    const float* queries = (const float*)d_in[0];
    const float* keys    = (const float*)d_in[1];
    const float* values  = (const float*)d_in[2];
    const float* prev    = (const float*)d_in[3];
    const int*   mask    = (const int*)d_in[4];
    const float* Wq_w = (const float*)d_in[5];
    const float* Wq_b = (const float*)d_in[6];
    const float* Wk_w = (const float*)d_in[7];
    const float* Wk_b = (const float*)d_in[8];
    const float* Wv_w = (const float*)d_in[9];
    const float* Wv_b = (const float*)d_in[10];
    const float* Wo_w = (const float*)d_in[11];
    const float* Wo_b = (const float*)d_in[12];
    const float* gat  = (const float*)d_in[13];

    float* out    = (float*)d_out;
    float* scores = out + (size_t)Bdim * Ldim * HIDdim;

    cudaFuncSetAttribute(fused_attn,
                         cudaFuncAttributeMaxDynamicSharedMemorySize, SMEM_FUSED);
    cudaFuncSetAttribute(qkv_gemm,
                         cudaFuncAttributeMaxDynamicSharedMemorySize, GEMM_SMEM);
    cudaFuncSetAttribute(out_gemm,
                         cudaFuncAttributeMaxDynamicSharedMemorySize, GEMM_SMEM);

    qkv_gemm<<<768, 256, GEMM_SMEM>>>(queries, keys, values,
                                      Wq_w, Wq_b, Wk_w, Wk_b, Wv_w, Wv_b);

    dim3 gf(8, 64);
    fused_attn<<<gf, 256, SMEM_FUSED>>>(prev, mask, gat, scores);

    dim3 gproj(8, 32);
    out_gemm<<<gproj, 256, GEMM_SMEM>>>(Wo_w, Wo_b, out);
}